// round 16
// baseline (speedup 1.0000x reference)
#include <cuda_runtime.h>
#include <cuda_fp16.h>
#include <cstdint>

// ---------------------------------------------------------------------------
// Problem constants
// ---------------------------------------------------------------------------
#define T      6
#define H      40
#define W      72
#define C      512
#define NH     4
#define HD     128
#define WH_    5
#define WW_    9
#define NWIN   64
#define S_     45
#define NROLL  148
#define P_     180
#define KTOT   373
#define TKEYS  (T*KTOT)   // 2238
#define TOK    (T*H*W)    // 17280
#define PTOK   (T*P_)     // 1080
#define SCALE  0.08838834764831845f
#define SCL2E  (0.08838834764831845f * 1.4426950408889634f)
#define NITEMS (NWIN * NH * 3)   // 768 attention work items

// ---------------------------------------------------------------------------
// Scratch (device globals)
// ---------------------------------------------------------------------------
__device__ __half g_xh[TOK * C];
__device__ __half g_qh[TOK * C];
__device__ __half g_kc[(TOK + PTOK) * C];
__device__ __half g_vc[(TOK + PTOK) * C];
__device__ __half g_yh[TOK * C];
__device__ __half g_pxh[PTOK * C];
__device__ __half g_wqh[C * C];
__device__ __half g_wkh[C * C];
__device__ __half g_wvh[C * C];
__device__ __half g_wph[C * C];
__device__ int    g_tofs[NWIN * TKEYS];
__device__ int    g_wmask[NWIN];
__device__ int    g_worder[NWIN];

// ---------------------------------------------------------------------------
// Helpers
// ---------------------------------------------------------------------------
__device__ __forceinline__ void cpasync16(uint32_t dst, const void* src) {
    asm volatile("cp.async.cg.shared.global [%0], [%1], 16;\n"
                 :: "r"(dst), "l"(src));
}

__device__ __forceinline__ void cpasync16z(uint32_t dst, const void* src, int src_sz) {
    asm volatile("cp.async.cg.shared.global [%0], [%1], 16, %2;\n"
                 :: "r"(dst), "l"(src), "r"(src_sz));
}

__device__ __forceinline__ void mma_f16(float* c, uint32_t a0, uint32_t a1,
                                        uint32_t a2, uint32_t a3,
                                        uint32_t b0, uint32_t b1) {
    asm volatile(
        "mma.sync.aligned.m16n8k16.row.col.f32.f16.f16.f32 "
        "{%0,%1,%2,%3}, {%4,%5,%6,%7}, {%8,%9}, {%0,%1,%2,%3};\n"
        : "+f"(c[0]), "+f"(c[1]), "+f"(c[2]), "+f"(c[3])
        : "r"(a0), "r"(a1), "r"(a2), "r"(a3), "r"(b0), "r"(b1));
}

__device__ __forceinline__ void ldsm_x4(uint32_t& r0, uint32_t& r1,
                                        uint32_t& r2, uint32_t& r3, uint32_t addr) {
    asm volatile("ldmatrix.sync.aligned.m8n8.x4.shared.b16 {%0,%1,%2,%3}, [%4];"
                 : "=r"(r0), "=r"(r1), "=r"(r2), "=r"(r3) : "r"(addr));
}

__device__ __forceinline__ void ldsm_x2(uint32_t& r0, uint32_t& r1, uint32_t addr) {
    asm volatile("ldmatrix.sync.aligned.m8n8.x2.shared.b16 {%0,%1}, [%2];"
                 : "=r"(r0), "=r"(r1) : "r"(addr));
}

__device__ __forceinline__ void ldsm_x2_trans(uint32_t& r0, uint32_t& r1, uint32_t addr) {
    asm volatile("ldmatrix.sync.aligned.m8n8.x2.trans.shared.b16 {%0,%1}, [%2];"
                 : "=r"(r0), "=r"(r1) : "r"(addr));
}

__device__ __forceinline__ uint32_t smem_u32(const void* p) {
    return (uint32_t)__cvta_generic_to_shared(p);
}

__device__ __forceinline__ uint32_t h2u(float a, float b) {
    __half2 h = __floats2half2_rn(a, b);
    return *(uint32_t*)&h;
}

__device__ __forceinline__ float ex2a(float x) {
    float y;
    asm("ex2.approx.ftz.f32 %0, %1;" : "=f"(y) : "f"(x));
    return y;
}

__device__ __forceinline__ uint32_t ex2h2(float a, float b) {
    uint32_t d = h2u(a, b), e;
    asm("ex2.approx.f16x2 %0, %1;" : "=r"(e) : "r"(d));
    return e;
}

// ---------------------------------------------------------------------------
// Merged preamble: conv_x [0,8640) | conv_wT [8640,9664) | pool [9664,10744)
//                  | init_idx [10744,10808) | wmask {10808}
// ---------------------------------------------------------------------------
#define PB_CONVX  8640
#define PB_WT     (PB_CONVX + 1024)
#define PB_POOL   (PB_WT + 1080)
#define PB_IDX    (PB_POOL + 64)
#define PB_TOTAL  (PB_IDX + 1)

__global__ __launch_bounds__(256) void preamble_kernel(
    const float* __restrict__ x, const float* __restrict__ masks,
    const float* __restrict__ w0, const float* __restrict__ w1,
    const float* __restrict__ w2, const float* __restrict__ w3,
    const float* __restrict__ pw, const float* __restrict__ pb)
{
    __shared__ float t[32][33];
    __shared__ int ish[NROLL];
    const int b = blockIdx.x;

    if (b < PB_CONVX) {                   // ---- conv_x: fp32 -> half ----
        int i = b * 256 + threadIdx.x;
        float4 v = ((const float4*)x)[i];
        ((uint32_t*)g_xh)[i * 2 + 0] = h2u(v.x, v.y);
        ((uint32_t*)g_xh)[i * 2 + 1] = h2u(v.z, v.w);
    } else if (b < PB_WT) {               // ---- conv_wT ----
        int bb = b - PB_CONVX;
        int m = bb >> 8;
        const float* src = (m == 0) ? w0 : (m == 1) ? w1 : (m == 2) ? w2 : w3;
        __half* dst = (m == 0) ? g_wqh : (m == 1) ? g_wkh : (m == 2) ? g_wvh : g_wph;
        int bx = (bb & 15) * 32, by = ((bb >> 4) & 15) * 32;
        int tx = threadIdx.x & 31, ty0 = threadIdx.x >> 5;
#pragma unroll
        for (int i = 0; i < 4; i++) {
            int ty = ty0 + i * 8;
            t[ty][tx] = src[(size_t)(by + ty) * C + bx + tx];
        }
        __syncthreads();
#pragma unroll
        for (int i = 0; i < 4; i++) {
            int ty = ty0 + i * 8;
            dst[(size_t)(bx + ty) * C + by + tx] = __float2half_rn(t[tx][ty]);
        }
    } else if (b < PB_POOL) {             // ---- pool conv ----
        int o = b - PB_WT;
        int f = o / 180, r = o % 180;
        int py = r / 18, pxx = r % 18;
        for (int c = threadIdx.x; c < C; c += 256) {
            float s = pb[c];
#pragma unroll
            for (int i = 0; i < 4; i++)
#pragma unroll
                for (int j = 0; j < 4; j++)
                    s += x[((size_t)(f * H + py * 4 + i) * W + (pxx * 4 + j)) * C + c]
                         * pw[(i * 4 + j) * C + c];
            g_pxh[(size_t)o * C + c] = __float2half_rn(s);
        }
    } else if (b < PB_IDX) {              // ---- init_idx ----
        if (threadIdx.x == 0) {
            int cnt = 0;
            for (int s = 0; s < 4; s++)
                for (int i = 0; i < WH_; i++)
                    for (int j = 0; j < WW_; j++) {
                        bool inval;
                        if (s == 0)      inval = (i < 2 && j < 4);
                        else if (s == 1) inval = (i < 2 && j >= 5);
                        else if (s == 2) inval = (i >= 3 && j < 4);
                        else             inval = (i >= 3 && j >= 5);
                        if (!inval) ish[cnt++] = s * 45 + i * 9 + j;
                    }
        }
        __syncthreads();
        int win = b - PB_POOL;
        int wy = win >> 3, wx = win & 7;
        for (int g = threadIdx.x; g < TKEYS; g += 256) {
            int f = g / KTOT, j = g - f * KTOT;
            int tok;
            if (j < S_) {
                int i = j / 9, jj = j % 9;
                tok = f * (H * W) + (wy * WH_ + i) * W + (wx * WW_ + jj);
            } else if (j < S_ + NROLL) {
                int v = ish[j - S_];
                int s = v / 45, pos = v % 45;
                int i = pos / 9, jj = pos % 9;
                int s0 = (s < 2) ? -3 : 3;
                int s1 = ((s & 1) == 0) ? -5 : 5;
                int y = wy * WH_ + i, xx2 = wx * WW_ + jj;
                int yy = ((y - s0) % H + H) % H;
                int xx = ((xx2 - s1) % W + W) % W;
                tok = f * (H * W) + yy * W + xx;
            } else {
                tok = TOK + f * P_ + (j - S_ - NROLL);
            }
            g_tofs[win * TKEYS + g] = tok;
        }
    } else {                              // ---- wmask + worder ----
        int win = threadIdx.x;
        if (win < NWIN) {
            int wy = win >> 3, wx = win & 7;
            float s = 0.f;
            for (int f = 0; f < T; f++)
                for (int i = 0; i < WH_; i++)
                    for (int j = 0; j < WW_; j++)
                        s += masks[(size_t)(f * H + wy * WH_ + i) * W + (wx * WW_ + j)];
            int m = (s > 0.f) ? 1 : 0;
            g_wmask[win] = m;
            ish[win] = m;
        }
        __syncthreads();
        if (threadIdx.x == 0) {
            int pos = 0;
            for (int i = 0; i < NWIN; i++) if (ish[i])  g_worder[pos++] = i;
            for (int i = 0; i < NWIN; i++) if (!ish[i]) g_worder[pos++] = i;
        }
    }
}

// ---------------------------------------------------------------------------
// fp16 GEMM body
// ---------------------------------------------------------------------------
#define GH_ROW   72
#define GH_TILEB (128 * GH_ROW * 2)
#define GH_SMEM  (4 * GH_TILEB)

__device__ __forceinline__ void gemm_body(
    const __half* __restrict__ A, const __half* __restrict__ Bt,
    const float* __restrict__ bias, __half* __restrict__ Ch,
    float* __restrict__ Cf, int M, int row0, int write_half, char* smc)
{
    __half* a_sm = (__half*)smc;
    __half* b_sm = (__half*)(smc + 2 * GH_TILEB);
    const int tid  = threadIdx.x;
    const int lane = tid & 31, warp = tid >> 5;
    const int grp  = lane >> 2, tg = lane & 3;
    const int mb = (warp >> 2) * 64, nb = (warp & 3) * 32;
    const int col0 = blockIdx.x * 128;

    const uint32_t sA = smem_u32(a_sm);
    const uint32_t sB = smem_u32(b_sm);

    const uint32_t aBase = sA + (mb + (lane & 15)) * (GH_ROW * 2) + (lane >> 4) * 16;
    const uint32_t bBase = sB + (nb + ((lane >> 4) & 1) * 8 + (lane & 7)) * (GH_ROW * 2)
                              + ((lane >> 3) & 1) * 16;

    float acc[4][4][4];
#pragma unroll
    for (int i = 0; i < 4; i++)
#pragma unroll
        for (int j = 0; j < 4; j++)
#pragma unroll
            for (int r = 0; r < 4; r++) acc[i][j][r] = 0.f;

    auto load_tile = [&](int kt, int b) {
#pragma unroll
        for (int i = 0; i < 4; i++) {
            int idx = i * 256 + tid;
            int r = idx >> 3, seg = idx & 7;
            int gr = row0 + r; if (gr > M - 1) gr = M - 1;
            cpasync16(sA + b * GH_TILEB + r * (GH_ROW * 2) + seg * 16,
                      A + (size_t)gr * 512 + kt * 64 + seg * 8);
        }
#pragma unroll
        for (int i = 0; i < 4; i++) {
            int idx = i * 256 + tid;
            int r = idx >> 3, seg = idx & 7;
            cpasync16(sB + b * GH_TILEB + r * (GH_ROW * 2) + seg * 16,
                      Bt + (size_t)(col0 + r) * 512 + kt * 64 + seg * 8);
        }
        asm volatile("cp.async.commit_group;\n");
    };

    load_tile(0, 0);

    for (int it = 0; it < 8; it++) {
        if (it < 7) {
            load_tile(it + 1, (it & 1) ^ 1);
            asm volatile("cp.async.wait_group 1;\n");
        } else {
            asm volatile("cp.async.wait_group 0;\n");
        }
        __syncthreads();
        const uint32_t bufoff = (uint32_t)((it & 1) * GH_TILEB);
#pragma unroll
        for (int s = 0; s < 4; s++) {
            uint32_t af[4][4];
#pragma unroll
            for (int mt = 0; mt < 4; mt++)
                ldsm_x4(af[mt][0], af[mt][1], af[mt][2], af[mt][3],
                        aBase + bufoff + mt * 16 * (GH_ROW * 2) + s * 32);
            uint32_t bf[2][4];
#pragma unroll
            for (int p = 0; p < 2; p++)
                ldsm_x4(bf[p][0], bf[p][1], bf[p][2], bf[p][3],
                        bBase + bufoff + p * 16 * (GH_ROW * 2) + s * 32);
#pragma unroll
            for (int nt = 0; nt < 4; nt++) {
                uint32_t b0 = bf[nt >> 1][(nt & 1) * 2];
                uint32_t b1 = bf[nt >> 1][(nt & 1) * 2 + 1];
#pragma unroll
                for (int mt = 0; mt < 4; mt++)
                    mma_f16(acc[mt][nt], af[mt][0], af[mt][1], af[mt][2], af[mt][3], b0, b1);
            }
        }
        __syncthreads();
    }

#pragma unroll
    for (int mt = 0; mt < 4; mt++) {
        int r0 = row0 + mb + mt * 16 + grp;
#pragma unroll
        for (int nt = 0; nt < 4; nt++) {
            int cc = col0 + nb + nt * 8 + tg * 2;
            float b0v = bias[cc], b1v = bias[cc + 1];
            float o0 = acc[mt][nt][0] + b0v, o1 = acc[mt][nt][1] + b1v;
            float o2 = acc[mt][nt][2] + b0v, o3 = acc[mt][nt][3] + b1v;
            if (write_half) {
                if (r0 < M)     *(uint32_t*)&Ch[(size_t)r0 * 512 + cc]       = h2u(o0, o1);
                if (r0 + 8 < M) *(uint32_t*)&Ch[(size_t)(r0 + 8) * 512 + cc] = h2u(o2, o3);
            } else {
                if (r0 < M)     *(float2*)(Cf + (size_t)r0 * 512 + cc)       = make_float2(o0, o1);
                if (r0 + 8 < M) *(float2*)(Cf + (size_t)(r0 + 8) * 512 + cc) = make_float2(o2, o3);
            }
        }
    }
}

__global__ __launch_bounds__(256, 2) void gemm_h(
    const __half* __restrict__ A, const __half* __restrict__ Bt,
    const float* __restrict__ bias, float* __restrict__ Cf, int M)
{
    extern __shared__ char smc[];
    gemm_body(A, Bt, bias, nullptr, Cf, M, blockIdx.y * 128, 0, smc);
}

__global__ __launch_bounds__(256, 2) void gemm_qkv(
    const __half* __restrict__ xh, const __half* __restrict__ pxh,
    const __half* __restrict__ B0, const __half* __restrict__ B1,
    const __half* __restrict__ B2,
    const float* __restrict__ b0, const float* __restrict__ b1,
    const float* __restrict__ b2,
    __half* __restrict__ C0, __half* __restrict__ C1, __half* __restrict__ C2)
{
    extern __shared__ char smc[];
    const int z = blockIdx.z;
    const bool pooled = (blockIdx.y >= 135);
    if (pooled && z == 0) return;
    const __half* Bt  = (z == 0) ? B0 : (z == 1) ? B1 : B2;
    const float* bias = (z == 0) ? b0 : (z == 1) ? b1 : b2;
    __half* Ch = (z == 0) ? C0 : (z == 1) ? C1 : C2;
    if (pooled) Ch += (size_t)TOK * C;
    const __half* A = pooled ? pxh : xh;
    const int M    = pooled ? PTOK : TOK;
    const int row0 = (pooled ? (blockIdx.y - 135) : blockIdx.y) * 128;
    gemm_body(A, Bt, bias, Ch, nullptr, M, row0, 1, smc);
}

// ---------------------------------------------------------------------------
// Attention v12: static 1D grid over 768 items, globally masked-first order.
//   item = blockIdx.x; ord = item/12 (window rank), 12 items per window
//   consecutive (L2 reuse of the window's gather footprint).
// ---------------------------------------------------------------------------
#define KVS2 136
#define KC   64
#define QF_BYTES 24576
#define KBUF (KC * KVS2 * 2)
#define ATTN_SMEM (QF_BYTES + 4 * KBUF)   // 94208

__global__ __launch_bounds__(192, 2) void attn_h()
{
    const int item = blockIdx.x;
    const int ord  = item / 12;
    const int r12  = item - ord * 12;
    const int fp   = r12 >> 2;         // 0..2
    const int head = r12 & 3;          // 0..3
    const int win  = g_worder[ord];

    const int tid  = threadIdx.x;
    const int lane = tid & 31, w = tid >> 5;
    const int grp  = lane >> 2, tg = lane & 3;
    extern __shared__ char smc[];
    uint32_t* qf  = (uint32_t*)smc;
    __half*   k_s = (__half*)(smc + QF_BYTES);
    __half*   v_s = (__half*)(smc + QF_BYTES + 2 * KBUF);
    const uint32_t kb = smem_u32(k_s), vb = smem_u32(v_s);

    const uint32_t kq2Base  = kb + (lane & 7) * (KVS2 * 2) + ((lane >> 3) & 1) * 16;
    const uint32_t pvBase   = vb + (lane & 15) * (KVS2 * 2) + (lane >> 4) * 16;
    const uint32_t ones_base= vb + (lane & 15) * (KVS2 * 2) + 256;

    const int wy = win >> 3, wx = win & 7;
    const int masked = g_wmask[win];
    const int nch    = masked ? (TKEYS + KC - 1) / KC : 2;
    const int* tof   = g_tofs + win * TKEYS;

    if (tid < 128) {
        int buf = tid >> 6, key = tid & 63;
        *(uint32_t*)&v_s[buf * KC * KVS2 + key * KVS2 + 128] = h2u(1.f, 0.f);
    }

    const __half2 sc2 = __floats2half2_rn(SCL2E, SCL2E);
    for (int idx = tid; idx < 96 * 16; idx += 192) {
        int row = idx >> 4, seg8 = idx & 15;
        int qi = row % 48;
        int frame = fp * 2 + (row >= 48 ? 1 : 0);
        uint4 v = make_uint4(0u, 0u, 0u, 0u);
        if (qi < 45) {
            int y = wy * WH_ + qi / 9, x = wx * WW_ + qi % 9;
            v = *(const uint4*)(g_qh + ((size_t)(frame * H + y) * W + x) * C
                                + head * HD + seg8 * 8);
            __half2* hh = (__half2*)&v;
            hh[0] = __hmul2(hh[0], sc2); hh[1] = __hmul2(hh[1], sc2);
            hh[2] = __hmul2(hh[2], sc2); hh[3] = __hmul2(hh[3], sc2);
        }
        int mt = row >> 4, rr = row & 15;
        int rg = rr & 7, hi = rr >> 3;
        int s = seg8 >> 1, lo8 = seg8 & 1;
        int comp = hi + 2 * lo8;
        uint32_t* base = qf + ((mt * 8 + s) * 32 + rg * 4) * 4 + comp;
        base[0]  = v.x;
        base[4]  = v.y;
        base[8]  = v.z;
        base[12] = v.w;
    }

    float acc[16][4];
#pragma unroll
    for (int i = 0; i < 16; i++)
#pragma unroll
        for (int r = 0; r < 4; r++) acc[i][r] = 0.f;
    float accE[4] = {0.f, 0.f, 0.f, 0.f};
    float m0 = -1e30f, m1 = -1e30f;

    auto gather = [&](int cc, int buf) {
        for (int e = tid; e < KC * 16; e += 192) {
            int key = e >> 4, seg = e & 15;
            int g2;
            bool valid;
            if (masked) { g2 = cc * KC + key; valid = (g2 < TKEYS); }
            else        { g2 = (fp * 2 + cc) * KTOT + key; valid = (key < S_); }
            const __half *ksrc = g_kc, *vsrc = g_vc;
            int sz = 0;
            if (valid) {
                size_t off = (size_t)tof[g2] * C + head * HD + seg * 8;
                ksrc = g_kc + off; vsrc = g_vc + off;
                sz = 16;
            }
            uint32_t d = (uint32_t)(buf * KBUF + key * (KVS2 * 2) + seg * 16);
            cpasync16z(kb + d, ksrc, sz);
            cpasync16z(vb + d, vsrc, sz);
        }
        asm volatile("cp.async.commit_group;\n");
    };

    gather(0, 0);

    for (int cc = 0; cc < nch; cc++) {
        asm volatile("cp.async.wait_group 0;\n");
        __syncthreads();
        const int buf = cc & 1;
        const uint32_t bufoff = (uint32_t)(buf * KBUF);
        if (cc + 1 < nch) gather(cc + 1, buf ^ 1);

        if (masked || ((w >= 3) == (cc == 1))) {
            const int rem = masked ? min(KC, TKEYS - cc * KC) : S_;

            float c[8][4];
#pragma unroll
            for (int nt = 0; nt < 8; nt++)
#pragma unroll
                for (int r = 0; r < 4; r++) c[nt][r] = 0.f;
#pragma unroll
            for (int s = 0; s < 8; s++) {
                uint4 a = ((const uint4*)qf)[(w * 8 + s) * 32 + lane];
#pragma unroll
                for (int nt = 0; nt < 8; nt++) {
                    uint32_t b0, b1;
                    ldsm_x2(b0, b1,
                            kq2Base + bufoff + nt * 8 * (KVS2 * 2) + s * 32);
                    mma_f16(c[nt], a.x, a.y, a.z, a.w, b0, b1);
                }
            }

            if (rem < KC) {
#pragma unroll
                for (int nt = 0; nt < 8; nt++) {
                    int k0 = nt * 8 + tg * 2;
                    if (k0 >= rem)     { c[nt][0] = -1e30f; c[nt][2] = -1e30f; }
                    if (k0 + 1 >= rem) { c[nt][1] = -1e30f; c[nt][3] = -1e30f; }
                }
            }

            float r0 = -1e30f, r1 = -1e30f;
#pragma unroll
            for (int nt = 0; nt < 8; nt++) {
                r0 = fmaxf(r0, fmaxf(c[nt][0], c[nt][1]));
                r1 = fmaxf(r1, fmaxf(c[nt][2], c[nt][3]));
            }
            r0 = fmaxf(r0, __shfl_xor_sync(0xffffffffu, r0, 1));
            r0 = fmaxf(r0, __shfl_xor_sync(0xffffffffu, r0, 2));
            r1 = fmaxf(r1, __shfl_xor_sync(0xffffffffu, r1, 1));
            r1 = fmaxf(r1, __shfl_xor_sync(0xffffffffu, r1, 2));
            float m0n = fmaxf(m0, r0), m1n = fmaxf(m1, r1);

            uint32_t pk[8][2];
#pragma unroll
            for (int nt = 0; nt < 8; nt++) {
                pk[nt][0] = ex2h2(c[nt][0] - m0n, c[nt][1] - m0n);
                pk[nt][1] = ex2h2(c[nt][2] - m1n, c[nt][3] - m1n);
            }

            bool same = (m0n == m0) && (m1n == m1);
            if (!__all_sync(0xffffffffu, same)) {
                float corr0 = ex2a(m0 - m0n), corr1 = ex2a(m1 - m1n);
#pragma unroll
                for (int nt2 = 0; nt2 < 16; nt2++) {
                    acc[nt2][0] *= corr0; acc[nt2][1] *= corr0;
                    acc[nt2][2] *= corr1; acc[nt2][3] *= corr1;
                }
                accE[0] *= corr0; accE[1] *= corr0;
                accE[2] *= corr1; accE[3] *= corr1;
            }
            m0 = m0n; m1 = m1n;

#pragma unroll
            for (int ks = 0; ks < 4; ks++) {
                uint32_t a0 = pk[2 * ks][0],     a1 = pk[2 * ks][1];
                uint32_t a2 = pk[2 * ks + 1][0], a3 = pk[2 * ks + 1][1];
#pragma unroll
                for (int nt2 = 0; nt2 < 16; nt2++) {
                    uint32_t b0, b1;
                    ldsm_x2_trans(b0, b1,
                                  pvBase + bufoff + ks * 16 * (KVS2 * 2) + nt2 * 16);
                    mma_f16(acc[nt2], a0, a1, a2, a3, b0, b1);
                }
                uint32_t e0, e1;
                ldsm_x2_trans(e0, e1, ones_base + bufoff + ks * 16 * (KVS2 * 2));
                mma_f16(accE, a0, a1, a2, a3, e0, e1);
            }
        }
    }

    float l0 = __shfl_sync(0xffffffffu, accE[0], lane & ~3);
    float l1 = __shfl_sync(0xffffffffu, accE[2], lane & ~3);
#pragma unroll
    for (int hh = 0; hh < 2; hh++) {
        int row = w * 16 + grp + hh * 8;
        int qi = row % 48;
        if (qi < 45) {
            int frame = fp * 2 + (row >= 48 ? 1 : 0);
            float inv = 1.f / (hh ? l1 : l0);
            int y = wy * WH_ + qi / 9, x = wx * WW_ + qi % 9;
            __half* yp = g_yh + ((size_t)(frame * H + y) * W + x) * C + head * HD;
#pragma unroll
            for (int nt2 = 0; nt2 < 16; nt2++) {
                float o0 = acc[nt2][hh * 2 + 0] * inv;
                float o1 = acc[nt2][hh * 2 + 1] * inv;
                *(uint32_t*)(yp + nt2 * 8 + tg * 2) = h2u(o0, o1);
            }
        }
    }
}

// ---------------------------------------------------------------------------
// Launcher
// ---------------------------------------------------------------------------
extern "C" void kernel_launch(void* const* d_in, const int* in_sizes, int n_in,
                              void* d_out, int out_size)
{
    const float* x     = (const float*)d_in[0];
    const float* masks = (const float*)d_in[1];
    const float* Wq    = (const float*)d_in[2];
    const float* bq    = (const float*)d_in[3];
    const float* Wk    = (const float*)d_in[4];
    const float* bk    = (const float*)d_in[5];
    const float* Wv    = (const float*)d_in[6];
    const float* bv    = (const float*)d_in[7];
    const float* Wp    = (const float*)d_in[8];
    const float* bp    = (const float*)d_in[9];
    const float* pw    = (const float*)d_in[10];
    const float* pb    = (const float*)d_in[11];
    float* out = (float*)d_out;

    __half *xh, *qh, *kc, *vc, *yh, *pxh, *wqh, *wkh, *wvh, *wph;
    cudaGetSymbolAddress((void**)&xh,  g_xh);
    cudaGetSymbolAddress((void**)&qh,  g_qh);
    cudaGetSymbolAddress((void**)&kc,  g_kc);
    cudaGetSymbolAddress((void**)&vc,  g_vc);
    cudaGetSymbolAddress((void**)&yh,  g_yh);
    cudaGetSymbolAddress((void**)&pxh, g_pxh);
    cudaGetSymbolAddress((void**)&wqh, g_wqh);
    cudaGetSymbolAddress((void**)&wkh, g_wkh);
    cudaGetSymbolAddress((void**)&wvh, g_wvh);
    cudaGetSymbolAddress((void**)&wph, g_wph);

    cudaFuncSetAttribute(gemm_h,   cudaFuncAttributeMaxDynamicSharedMemorySize, GH_SMEM);
    cudaFuncSetAttribute(gemm_qkv, cudaFuncAttributeMaxDynamicSharedMemorySize, GH_SMEM);
    cudaFuncSetAttribute(attn_h,   cudaFuncAttributeMaxDynamicSharedMemorySize, ATTN_SMEM);

    preamble_kernel<<<PB_TOTAL, 256>>>(x, masks, Wq, Wk, Wv, Wp, pw, pb);

    gemm_qkv<<<dim3(4, 144, 3), 256, GH_SMEM>>>(
        xh, pxh, wqh, wkh, wvh, bq, bk, bv, qh, kc, vc);

    attn_h<<<NITEMS, 192, ATTN_SMEM>>>();

    gemm_h<<<dim3(4, TOK / 128), 256, GH_SMEM>>>(yh, wph, bp, out, TOK);
}

// round 17
// speedup vs baseline: 1.0298x; 1.0298x over previous
#include <cuda_runtime.h>
#include <cuda_fp16.h>
#include <cstdint>

// ---------------------------------------------------------------------------
// Problem constants
// ---------------------------------------------------------------------------
#define T      6
#define H      40
#define W      72
#define C      512
#define NH     4
#define HD     128
#define WH_    5
#define WW_    9
#define NWIN   64
#define S_     45
#define NROLL  148
#define P_     180
#define KTOT   373
#define TKEYS  (T*KTOT)   // 2238
#define TOK    (T*H*W)    // 17280
#define PTOK   (T*P_)     // 1080
#define SCALE  0.08838834764831845f
#define SCL2E  (0.08838834764831845f * 1.4426950408889634f)

// ---------------------------------------------------------------------------
// Scratch (device globals)
// ---------------------------------------------------------------------------
__device__ __half g_xh[TOK * C];
__device__ __half g_qh[TOK * C];
__device__ __half g_kc[(TOK + PTOK) * C];
__device__ __half g_vc[(TOK + PTOK) * C];
__device__ __half g_yh[TOK * C];
__device__ __half g_pxh[PTOK * C];
__device__ __half g_wqh[C * C];
__device__ __half g_wkh[C * C];
__device__ __half g_wvh[C * C];
__device__ __half g_wph[C * C];
__device__ int    g_tofs[NWIN * TKEYS];
__device__ int    g_wmask[NWIN];
__device__ int    g_worder[NWIN];

// ---------------------------------------------------------------------------
// Helpers
// ---------------------------------------------------------------------------
__device__ __forceinline__ void cpasync16(uint32_t dst, const void* src) {
    asm volatile("cp.async.cg.shared.global [%0], [%1], 16;\n"
                 :: "r"(dst), "l"(src));
}

__device__ __forceinline__ void cpasync16z(uint32_t dst, const void* src, int src_sz) {
    asm volatile("cp.async.cg.shared.global [%0], [%1], 16, %2;\n"
                 :: "r"(dst), "l"(src), "r"(src_sz));
}

__device__ __forceinline__ void mma_f16(float* c, uint32_t a0, uint32_t a1,
                                        uint32_t a2, uint32_t a3,
                                        uint32_t b0, uint32_t b1) {
    asm volatile(
        "mma.sync.aligned.m16n8k16.row.col.f32.f16.f16.f32 "
        "{%0,%1,%2,%3}, {%4,%5,%6,%7}, {%8,%9}, {%0,%1,%2,%3};\n"
        : "+f"(c[0]), "+f"(c[1]), "+f"(c[2]), "+f"(c[3])
        : "r"(a0), "r"(a1), "r"(a2), "r"(a3), "r"(b0), "r"(b1));
}

__device__ __forceinline__ void ldsm_x4(uint32_t& r0, uint32_t& r1,
                                        uint32_t& r2, uint32_t& r3, uint32_t addr) {
    asm volatile("ldmatrix.sync.aligned.m8n8.x4.shared.b16 {%0,%1,%2,%3}, [%4];"
                 : "=r"(r0), "=r"(r1), "=r"(r2), "=r"(r3) : "r"(addr));
}

__device__ __forceinline__ void ldsm_x2(uint32_t& r0, uint32_t& r1, uint32_t addr) {
    asm volatile("ldmatrix.sync.aligned.m8n8.x2.shared.b16 {%0,%1}, [%2];"
                 : "=r"(r0), "=r"(r1) : "r"(addr));
}

__device__ __forceinline__ void ldsm_x2_trans(uint32_t& r0, uint32_t& r1, uint32_t addr) {
    asm volatile("ldmatrix.sync.aligned.m8n8.x2.trans.shared.b16 {%0,%1}, [%2];"
                 : "=r"(r0), "=r"(r1) : "r"(addr));
}

__device__ __forceinline__ uint32_t smem_u32(const void* p) {
    return (uint32_t)__cvta_generic_to_shared(p);
}

__device__ __forceinline__ uint32_t h2u(float a, float b) {
    __half2 h = __floats2half2_rn(a, b);
    return *(uint32_t*)&h;
}

__device__ __forceinline__ float ex2a(float x) {
    float y;
    asm("ex2.approx.ftz.f32 %0, %1;" : "=f"(y) : "f"(x));
    return y;
}

__device__ __forceinline__ uint32_t ex2h2(float a, float b) {
    uint32_t d = h2u(a, b), e;
    asm("ex2.approx.f16x2 %0, %1;" : "=r"(e) : "r"(d));
    return e;
}

// ---------------------------------------------------------------------------
// Merged preamble: conv_x [0,8640) | conv_wT [8640,9664) | pool [9664,10744)
//                  | init_idx [10744,10808) | wmask {10808}
// ---------------------------------------------------------------------------
#define PB_CONVX  8640
#define PB_WT     (PB_CONVX + 1024)
#define PB_POOL   (PB_WT + 1080)
#define PB_IDX    (PB_POOL + 64)
#define PB_TOTAL  (PB_IDX + 1)

__global__ __launch_bounds__(256) void preamble_kernel(
    const float* __restrict__ x, const float* __restrict__ masks,
    const float* __restrict__ w0, const float* __restrict__ w1,
    const float* __restrict__ w2, const float* __restrict__ w3,
    const float* __restrict__ pw, const float* __restrict__ pb)
{
    __shared__ float t[32][33];
    __shared__ int ish[NROLL];
    const int b = blockIdx.x;

    if (b < PB_CONVX) {                   // ---- conv_x: fp32 -> half ----
        int i = b * 256 + threadIdx.x;
        float4 v = ((const float4*)x)[i];
        ((uint32_t*)g_xh)[i * 2 + 0] = h2u(v.x, v.y);
        ((uint32_t*)g_xh)[i * 2 + 1] = h2u(v.z, v.w);
    } else if (b < PB_WT) {               // ---- conv_wT ----
        int bb = b - PB_CONVX;
        int m = bb >> 8;
        const float* src = (m == 0) ? w0 : (m == 1) ? w1 : (m == 2) ? w2 : w3;
        __half* dst = (m == 0) ? g_wqh : (m == 1) ? g_wkh : (m == 2) ? g_wvh : g_wph;
        int bx = (bb & 15) * 32, by = ((bb >> 4) & 15) * 32;
        int tx = threadIdx.x & 31, ty0 = threadIdx.x >> 5;
#pragma unroll
        for (int i = 0; i < 4; i++) {
            int ty = ty0 + i * 8;
            t[ty][tx] = src[(size_t)(by + ty) * C + bx + tx];
        }
        __syncthreads();
#pragma unroll
        for (int i = 0; i < 4; i++) {
            int ty = ty0 + i * 8;
            dst[(size_t)(bx + ty) * C + by + tx] = __float2half_rn(t[tx][ty]);
        }
    } else if (b < PB_POOL) {             // ---- pool conv ----
        int o = b - PB_WT;
        int f = o / 180, r = o % 180;
        int py = r / 18, pxx = r % 18;
        for (int c = threadIdx.x; c < C; c += 256) {
            float s = pb[c];
#pragma unroll
            for (int i = 0; i < 4; i++)
#pragma unroll
                for (int j = 0; j < 4; j++)
                    s += x[((size_t)(f * H + py * 4 + i) * W + (pxx * 4 + j)) * C + c]
                         * pw[(i * 4 + j) * C + c];
            g_pxh[(size_t)o * C + c] = __float2half_rn(s);
        }
    } else if (b < PB_IDX) {              // ---- init_idx ----
        if (threadIdx.x == 0) {
            int cnt = 0;
            for (int s = 0; s < 4; s++)
                for (int i = 0; i < WH_; i++)
                    for (int j = 0; j < WW_; j++) {
                        bool inval;
                        if (s == 0)      inval = (i < 2 && j < 4);
                        else if (s == 1) inval = (i < 2 && j >= 5);
                        else if (s == 2) inval = (i >= 3 && j < 4);
                        else             inval = (i >= 3 && j >= 5);
                        if (!inval) ish[cnt++] = s * 45 + i * 9 + j;
                    }
        }
        __syncthreads();
        int win = b - PB_POOL;
        int wy = win >> 3, wx = win & 7;
        for (int g = threadIdx.x; g < TKEYS; g += 256) {
            int f = g / KTOT, j = g - f * KTOT;
            int tok;
            if (j < S_) {
                int i = j / 9, jj = j % 9;
                tok = f * (H * W) + (wy * WH_ + i) * W + (wx * WW_ + jj);
            } else if (j < S_ + NROLL) {
                int v = ish[j - S_];
                int s = v / 45, pos = v % 45;
                int i = pos / 9, jj = pos % 9;
                int s0 = (s < 2) ? -3 : 3;
                int s1 = ((s & 1) == 0) ? -5 : 5;
                int y = wy * WH_ + i, xx2 = wx * WW_ + jj;
                int yy = ((y - s0) % H + H) % H;
                int xx = ((xx2 - s1) % W + W) % W;
                tok = f * (H * W) + yy * W + xx;
            } else {
                tok = TOK + f * P_ + (j - S_ - NROLL);
            }
            g_tofs[win * TKEYS + g] = tok;
        }
    } else {                              // ---- wmask + worder ----
        int win = threadIdx.x;
        if (win < NWIN) {
            int wy = win >> 3, wx = win & 7;
            float s = 0.f;
            for (int f = 0; f < T; f++)
                for (int i = 0; i < WH_; i++)
                    for (int j = 0; j < WW_; j++)
                        s += masks[(size_t)(f * H + wy * WH_ + i) * W + (wx * WW_ + j)];
            int m = (s > 0.f) ? 1 : 0;
            g_wmask[win] = m;
            ish[win] = m;
        }
        __syncthreads();
        if (threadIdx.x == 0) {
            int pos = 0;
            for (int i = 0; i < NWIN; i++) if (ish[i])  g_worder[pos++] = i;
            for (int i = 0; i < NWIN; i++) if (!ish[i]) g_worder[pos++] = i;
        }
    }
}

// ---------------------------------------------------------------------------
// fp16 GEMM body
// ---------------------------------------------------------------------------
#define GH_ROW   72
#define GH_TILEB (128 * GH_ROW * 2)
#define GH_SMEM  (4 * GH_TILEB)

__device__ __forceinline__ void gemm_body(
    const __half* __restrict__ A, const __half* __restrict__ Bt,
    const float* __restrict__ bias, __half* __restrict__ Ch,
    float* __restrict__ Cf, int M, int row0, int write_half, char* smc)
{
    __half* a_sm = (__half*)smc;
    __half* b_sm = (__half*)(smc + 2 * GH_TILEB);
    const int tid  = threadIdx.x;
    const int lane = tid & 31, warp = tid >> 5;
    const int grp  = lane >> 2, tg = lane & 3;
    const int mb = (warp >> 2) * 64, nb = (warp & 3) * 32;
    const int col0 = blockIdx.x * 128;

    const uint32_t sA = smem_u32(a_sm);
    const uint32_t sB = smem_u32(b_sm);

    const uint32_t aBase = sA + (mb + (lane & 15)) * (GH_ROW * 2) + (lane >> 4) * 16;
    const uint32_t bBase = sB + (nb + ((lane >> 4) & 1) * 8 + (lane & 7)) * (GH_ROW * 2)
                              + ((lane >> 3) & 1) * 16;

    float acc[4][4][4];
#pragma unroll
    for (int i = 0; i < 4; i++)
#pragma unroll
        for (int j = 0; j < 4; j++)
#pragma unroll
            for (int r = 0; r < 4; r++) acc[i][j][r] = 0.f;

    auto load_tile = [&](int kt, int b) {
#pragma unroll
        for (int i = 0; i < 4; i++) {
            int idx = i * 256 + tid;
            int r = idx >> 3, seg = idx & 7;
            int gr = row0 + r; if (gr > M - 1) gr = M - 1;
            cpasync16(sA + b * GH_TILEB + r * (GH_ROW * 2) + seg * 16,
                      A + (size_t)gr * 512 + kt * 64 + seg * 8);
        }
#pragma unroll
        for (int i = 0; i < 4; i++) {
            int idx = i * 256 + tid;
            int r = idx >> 3, seg = idx & 7;
            cpasync16(sB + b * GH_TILEB + r * (GH_ROW * 2) + seg * 16,
                      Bt + (size_t)(col0 + r) * 512 + kt * 64 + seg * 8);
        }
        asm volatile("cp.async.commit_group;\n");
    };

    load_tile(0, 0);

    for (int it = 0; it < 8; it++) {
        if (it < 7) {
            load_tile(it + 1, (it & 1) ^ 1);
            asm volatile("cp.async.wait_group 1;\n");
        } else {
            asm volatile("cp.async.wait_group 0;\n");
        }
        __syncthreads();
        const uint32_t bufoff = (uint32_t)((it & 1) * GH_TILEB);
#pragma unroll
        for (int s = 0; s < 4; s++) {
            uint32_t af[4][4];
#pragma unroll
            for (int mt = 0; mt < 4; mt++)
                ldsm_x4(af[mt][0], af[mt][1], af[mt][2], af[mt][3],
                        aBase + bufoff + mt * 16 * (GH_ROW * 2) + s * 32);
            uint32_t bf[2][4];
#pragma unroll
            for (int p = 0; p < 2; p++)
                ldsm_x4(bf[p][0], bf[p][1], bf[p][2], bf[p][3],
                        bBase + bufoff + p * 16 * (GH_ROW * 2) + s * 32);
#pragma unroll
            for (int nt = 0; nt < 4; nt++) {
                uint32_t b0 = bf[nt >> 1][(nt & 1) * 2];
                uint32_t b1 = bf[nt >> 1][(nt & 1) * 2 + 1];
#pragma unroll
                for (int mt = 0; mt < 4; mt++)
                    mma_f16(acc[mt][nt], af[mt][0], af[mt][1], af[mt][2], af[mt][3], b0, b1);
            }
        }
        __syncthreads();
    }

#pragma unroll
    for (int mt = 0; mt < 4; mt++) {
        int r0 = row0 + mb + mt * 16 + grp;
#pragma unroll
        for (int nt = 0; nt < 4; nt++) {
            int cc = col0 + nb + nt * 8 + tg * 2;
            float b0v = bias[cc], b1v = bias[cc + 1];
            float o0 = acc[mt][nt][0] + b0v, o1 = acc[mt][nt][1] + b1v;
            float o2 = acc[mt][nt][2] + b0v, o3 = acc[mt][nt][3] + b1v;
            if (write_half) {
                if (r0 < M)     *(uint32_t*)&Ch[(size_t)r0 * 512 + cc]       = h2u(o0, o1);
                if (r0 + 8 < M) *(uint32_t*)&Ch[(size_t)(r0 + 8) * 512 + cc] = h2u(o2, o3);
            } else {
                if (r0 < M)     *(float2*)(Cf + (size_t)r0 * 512 + cc)       = make_float2(o0, o1);
                if (r0 + 8 < M) *(float2*)(Cf + (size_t)(r0 + 8) * 512 + cc) = make_float2(o2, o3);
            }
        }
    }
}

__global__ __launch_bounds__(256, 2) void gemm_h(
    const __half* __restrict__ A, const __half* __restrict__ Bt,
    const float* __restrict__ bias, float* __restrict__ Cf, int M)
{
    extern __shared__ char smc[];
    gemm_body(A, Bt, bias, nullptr, Cf, M, blockIdx.y * 128, 0, smc);
}

__global__ __launch_bounds__(256, 2) void gemm_qkv(
    const __half* __restrict__ xh, const __half* __restrict__ pxh,
    const __half* __restrict__ B0, const __half* __restrict__ B1,
    const __half* __restrict__ B2,
    const float* __restrict__ b0, const float* __restrict__ b1,
    const float* __restrict__ b2,
    __half* __restrict__ C0, __half* __restrict__ C1, __half* __restrict__ C2)
{
    extern __shared__ char smc[];
    const int z = blockIdx.z;
    const bool pooled = (blockIdx.y >= 135);
    if (pooled && z == 0) return;
    const __half* Bt  = (z == 0) ? B0 : (z == 1) ? B1 : B2;
    const float* bias = (z == 0) ? b0 : (z == 1) ? b1 : b2;
    __half* Ch = (z == 0) ? C0 : (z == 1) ? C1 : C2;
    if (pooled) Ch += (size_t)TOK * C;
    const __half* A = pooled ? pxh : xh;
    const int M    = pooled ? PTOK : TOK;
    const int row0 = (pooled ? (blockIdx.y - 135) : blockIdx.y) * 128;
    gemm_body(A, Bt, bias, Ch, nullptr, M, row0, 1, smc);
}

// ---------------------------------------------------------------------------
// Attention v13: R14 3D-grid dispatch + hoisted ones-column fragment.
// ---------------------------------------------------------------------------
#define KVS2 136
#define KC   64
#define QF_BYTES 24576
#define KBUF (KC * KVS2 * 2)
#define ATTN_SMEM (QF_BYTES + 4 * KBUF)   // 94208

__global__ __launch_bounds__(192, 2) void attn_h()
{
    const int win = g_worder[blockIdx.x];
    const int head = blockIdx.y, fp = blockIdx.z;
    const int tid  = threadIdx.x;
    const int lane = tid & 31, w = tid >> 5;
    const int grp  = lane >> 2, tg = lane & 3;
    extern __shared__ char smc[];
    uint32_t* qf  = (uint32_t*)smc;
    __half*   k_s = (__half*)(smc + QF_BYTES);
    __half*   v_s = (__half*)(smc + QF_BYTES + 2 * KBUF);
    const uint32_t kb = smem_u32(k_s), vb = smem_u32(v_s);

    const uint32_t kq2Base  = kb + (lane & 7) * (KVS2 * 2) + ((lane >> 3) & 1) * 16;
    const uint32_t pvBase   = vb + (lane & 15) * (KVS2 * 2) + (lane >> 4) * 16;
    const uint32_t ones_base= vb + (lane & 15) * (KVS2 * 2) + 256;

    const int wy = win >> 3, wx = win & 7;
    const int masked = g_wmask[win];
    const int nch    = masked ? (TKEYS + KC - 1) / KC : 2;
    const int* tof   = g_tofs + win * TKEYS;

    // ones column: dims 128-135 = (1,0,0,0,0,0,0,0), both buffers (full 16B)
    if (tid < 128) {
        int buf = tid >> 6, key = tid & 63;
        *(uint4*)&v_s[buf * KC * KVS2 + key * KVS2 + 128] =
            make_uint4(h2u(1.f, 0.f), 0u, 0u, 0u);
    }

    const __half2 sc2 = __floats2half2_rn(SCL2E, SCL2E);
    for (int idx = tid; idx < 96 * 16; idx += 192) {
        int row = idx >> 4, seg8 = idx & 15;
        int qi = row % 48;
        int frame = fp * 2 + (row >= 48 ? 1 : 0);
        uint4 v = make_uint4(0u, 0u, 0u, 0u);
        if (qi < 45) {
            int y = wy * WH_ + qi / 9, x = wx * WW_ + qi % 9;
            v = *(const uint4*)(g_qh + ((size_t)(frame * H + y) * W + x) * C
                                + head * HD + seg8 * 8);
            __half2* hh = (__half2*)&v;
            hh[0] = __hmul2(hh[0], sc2); hh[1] = __hmul2(hh[1], sc2);
            hh[2] = __hmul2(hh[2], sc2); hh[3] = __hmul2(hh[3], sc2);
        }
        int mt = row >> 4, rr = row & 15;
        int rg = rr & 7, hi = rr >> 3;
        int s = seg8 >> 1, lo8 = seg8 & 1;
        int comp = hi + 2 * lo8;
        uint32_t* base = qf + ((mt * 8 + s) * 32 + rg * 4) * 4 + comp;
        base[0]  = v.x;
        base[4]  = v.y;
        base[8]  = v.z;
        base[12] = v.w;
    }
    __syncthreads();   // ones column + qf visible

    // hoisted ones fragment (identical for all ks / both buffers)
    uint32_t e0, e1;
    ldsm_x2_trans(e0, e1, ones_base);

    float acc[16][4];
#pragma unroll
    for (int i = 0; i < 16; i++)
#pragma unroll
        for (int r = 0; r < 4; r++) acc[i][r] = 0.f;
    float accE[4] = {0.f, 0.f, 0.f, 0.f};
    float m0 = -1e30f, m1 = -1e30f;

    auto gather = [&](int cc, int buf) {
        for (int e = tid; e < KC * 16; e += 192) {
            int key = e >> 4, seg = e & 15;
            int g2;
            bool valid;
            if (masked) { g2 = cc * KC + key; valid = (g2 < TKEYS); }
            else        { g2 = (fp * 2 + cc) * KTOT + key; valid = (key < S_); }
            const __half *ksrc = g_kc, *vsrc = g_vc;
            int sz = 0;
            if (valid) {
                size_t off = (size_t)tof[g2] * C + head * HD + seg * 8;
                ksrc = g_kc + off; vsrc = g_vc + off;
                sz = 16;
            }
            uint32_t d = (uint32_t)(buf * KBUF + key * (KVS2 * 2) + seg * 16);
            cpasync16z(kb + d, ksrc, sz);
            cpasync16z(vb + d, vsrc, sz);
        }
        asm volatile("cp.async.commit_group;\n");
    };

    gather(0, 0);

    for (int cc = 0; cc < nch; cc++) {
        asm volatile("cp.async.wait_group 0;\n");
        __syncthreads();
        const int buf = cc & 1;
        const uint32_t bufoff = (uint32_t)(buf * KBUF);
        if (cc + 1 < nch) gather(cc + 1, buf ^ 1);

        if (masked || ((w >= 3) == (cc == 1))) {
            const int rem = masked ? min(KC, TKEYS - cc * KC) : S_;

            float c[8][4];
#pragma unroll
            for (int nt = 0; nt < 8; nt++)
#pragma unroll
                for (int r = 0; r < 4; r++) c[nt][r] = 0.f;
#pragma unroll
            for (int s = 0; s < 8; s++) {
                uint4 a = ((const uint4*)qf)[(w * 8 + s) * 32 + lane];
#pragma unroll
                for (int nt = 0; nt < 8; nt++) {
                    uint32_t b0, b1;
                    ldsm_x2(b0, b1,
                            kq2Base + bufoff + nt * 8 * (KVS2 * 2) + s * 32);
                    mma_f16(c[nt], a.x, a.y, a.z, a.w, b0, b1);
                }
            }

            if (rem < KC) {
#pragma unroll
                for (int nt = 0; nt < 8; nt++) {
                    int k0 = nt * 8 + tg * 2;
                    if (k0 >= rem)     { c[nt][0] = -1e30f; c[nt][2] = -1e30f; }
                    if (k0 + 1 >= rem) { c[nt][1] = -1e30f; c[nt][3] = -1e30f; }
                }
            }

            float r0 = -1e30f, r1 = -1e30f;
#pragma unroll
            for (int nt = 0; nt < 8; nt++) {
                r0 = fmaxf(r0, fmaxf(c[nt][0], c[nt][1]));
                r1 = fmaxf(r1, fmaxf(c[nt][2], c[nt][3]));
            }
            r0 = fmaxf(r0, __shfl_xor_sync(0xffffffffu, r0, 1));
            r0 = fmaxf(r0, __shfl_xor_sync(0xffffffffu, r0, 2));
            r1 = fmaxf(r1, __shfl_xor_sync(0xffffffffu, r1, 1));
            r1 = fmaxf(r1, __shfl_xor_sync(0xffffffffu, r1, 2));
            float m0n = fmaxf(m0, r0), m1n = fmaxf(m1, r1);

            uint32_t pk[8][2];
#pragma unroll
            for (int nt = 0; nt < 8; nt++) {
                pk[nt][0] = ex2h2(c[nt][0] - m0n, c[nt][1] - m0n);
                pk[nt][1] = ex2h2(c[nt][2] - m1n, c[nt][3] - m1n);
            }

            bool same = (m0n == m0) && (m1n == m1);
            if (!__all_sync(0xffffffffu, same)) {
                float corr0 = ex2a(m0 - m0n), corr1 = ex2a(m1 - m1n);
#pragma unroll
                for (int nt2 = 0; nt2 < 16; nt2++) {
                    acc[nt2][0] *= corr0; acc[nt2][1] *= corr0;
                    acc[nt2][2] *= corr1; acc[nt2][3] *= corr1;
                }
                accE[0] *= corr0; accE[1] *= corr0;
                accE[2] *= corr1; accE[3] *= corr1;
            }
            m0 = m0n; m1 = m1n;

#pragma unroll
            for (int ks = 0; ks < 4; ks++) {
                uint32_t a0 = pk[2 * ks][0],     a1 = pk[2 * ks][1];
                uint32_t a2 = pk[2 * ks + 1][0], a3 = pk[2 * ks + 1][1];
#pragma unroll
                for (int nt2 = 0; nt2 < 16; nt2++) {
                    uint32_t b0, b1;
                    ldsm_x2_trans(b0, b1,
                                  pvBase + bufoff + ks * 16 * (KVS2 * 2) + nt2 * 16);
                    mma_f16(acc[nt2], a0, a1, a2, a3, b0, b1);
                }
                mma_f16(accE, a0, a1, a2, a3, e0, e1);
            }
        }
    }

    float l0 = __shfl_sync(0xffffffffu, accE[0], lane & ~3);
    float l1 = __shfl_sync(0xffffffffu, accE[2], lane & ~3);
#pragma unroll
    for (int hh = 0; hh < 2; hh++) {
        int row = w * 16 + grp + hh * 8;
        int qi = row % 48;
        if (qi < 45) {
            int frame = fp * 2 + (row >= 48 ? 1 : 0);
            float inv = 1.f / (hh ? l1 : l0);
            int y = wy * WH_ + qi / 9, x = wx * WW_ + qi % 9;
            __half* yp = g_yh + ((size_t)(frame * H + y) * W + x) * C + head * HD;
#pragma unroll
            for (int nt2 = 0; nt2 < 16; nt2++) {
                float o0 = acc[nt2][hh * 2 + 0] * inv;
                float o1 = acc[nt2][hh * 2 + 1] * inv;
                *(uint32_t*)(yp + nt2 * 8 + tg * 2) = h2u(o0, o1);
            }
        }
    }
}

// ---------------------------------------------------------------------------
// Launcher
// ---------------------------------------------------------------------------
extern "C" void kernel_launch(void* const* d_in, const int* in_sizes, int n_in,
                              void* d_out, int out_size)
{
    const float* x     = (const float*)d_in[0];
    const float* masks = (const float*)d_in[1];
    const float* Wq    = (const float*)d_in[2];
    const float* bq    = (const float*)d_in[3];
    const float* Wk    = (const float*)d_in[4];
    const float* bk    = (const float*)d_in[5];
    const float* Wv    = (const float*)d_in[6];
    const float* bv    = (const float*)d_in[7];
    const float* Wp    = (const float*)d_in[8];
    const float* bp    = (const float*)d_in[9];
    const float* pw    = (const float*)d_in[10];
    const float* pb    = (const float*)d_in[11];
    float* out = (float*)d_out;

    __half *xh, *qh, *kc, *vc, *yh, *pxh, *wqh, *wkh, *wvh, *wph;
    cudaGetSymbolAddress((void**)&xh,  g_xh);
    cudaGetSymbolAddress((void**)&qh,  g_qh);
    cudaGetSymbolAddress((void**)&kc,  g_kc);
    cudaGetSymbolAddress((void**)&vc,  g_vc);
    cudaGetSymbolAddress((void**)&yh,  g_yh);
    cudaGetSymbolAddress((void**)&pxh, g_pxh);
    cudaGetSymbolAddress((void**)&wqh, g_wqh);
    cudaGetSymbolAddress((void**)&wkh, g_wkh);
    cudaGetSymbolAddress((void**)&wvh, g_wvh);
    cudaGetSymbolAddress((void**)&wph, g_wph);

    cudaFuncSetAttribute(gemm_h,   cudaFuncAttributeMaxDynamicSharedMemorySize, GH_SMEM);
    cudaFuncSetAttribute(gemm_qkv, cudaFuncAttributeMaxDynamicSharedMemorySize, GH_SMEM);
    cudaFuncSetAttribute(attn_h,   cudaFuncAttributeMaxDynamicSharedMemorySize, ATTN_SMEM);

    preamble_kernel<<<PB_TOTAL, 256>>>(x, masks, Wq, Wk, Wv, Wp, pw, pb);

    gemm_qkv<<<dim3(4, 144, 3), 256, GH_SMEM>>>(
        xh, pxh, wqh, wkh, wvh, bq, bk, bv, qh, kc, vc);

    attn_h<<<dim3(NWIN, NH, 3), 192, ATTN_SMEM>>>();

    gemm_h<<<dim3(4, TOK / 128), 256, GH_SMEM>>>(yh, wph, bp, out, TOK);
}